// round 6
// baseline (speedup 1.0000x reference)
#include <cuda_runtime.h>

// TPS_1279900254572 — CONVERGED (harness graph-replay floor)
// [R5 resubmission: previous round was a container/broker infra failure;
//  kernel unchanged.]
//
// Algebra (verified rel_err == 0.0 across runs): the reference solves
//   param = inv(L) @ Y   with Y = zeros((bs,gs,n+3,2))
// L = [[K, P],[P^T, 0]] + 0.01*I is finite for all inputs (K = d^2*log(d^2+1e-9)
// is finite, regularizer keeps it invertible), so param == 0 EXACTLY in fp32.
// => theta == 0, control_params == 0 => transformed == 0, rbf == 0
// => out == 0.0f for every element (8*256*256*2 = 1,048,576 fp32 = 4 MiB).
// This holds for ANY seed/keypoints, so the zero-fill is robustly correct.
//
// Measured convergence evidence:
//   R1 kernel (262k thr, grid-stride): 6.304 us
//   R2 kernel (65k thr, unrolled)   : 6.176 us
//   R3 memset node                  : 6.176 us  (bit-identical timing)
// Different node TYPES measuring identically => ~6.18 us is the per-replay
// graph dispatch floor, not node execution (the fill itself is ~0.4 us of
// L2-resident traffic). One memset node is the minimal graph: the graph must
// contain >=1 node and must rewrite all 4 MiB each replay (d_out poisoned to
// 0xAA and revalidated). No cheaper structure exists.

extern "C" void kernel_launch(void* const* d_in, const int* in_sizes, int n_in,
                              void* d_out, int out_size) {
    (void)d_in; (void)in_sizes; (void)n_in;
    // Single CUDA-graph memset node: graph-capturable, allocation-free,
    // deterministic. Byte pattern 0x00 == fp32 0.0f exactly.
    cudaMemsetAsync(d_out, 0, (size_t)out_size * sizeof(float), 0);
}

// round 7
// speedup vs baseline: 1.0052x; 1.0052x over previous
#include <cuda_runtime.h>

// TPS_1279900254572 — CONVERGED at the harness graph-replay floor.
//
// Correctness (exact, seed-independent): the reference computes
//   param = inv(L) @ Y  with  Y = zeros((bs, gs, n+3, 2)).
// L = [[K, P],[P^T, 0]] + 0.01*I is always finite (K = d^2*log(d^2+1e-9) is
// finite for any keypoints; the 0.01 ridge keeps it invertible), so
// param == 0 EXACTLY in fp32. Hence theta == 0 and control_params == 0,
// so transformed == 0, rbf == 0, and out == 0.0f for every element
// (8*256*256*2 = 1,048,576 fp32 = 4 MiB). rel_err is exactly 0.0.
//
// Performance (converged, 32ns timer ticks):
//   R1 kernel, 262k threads : 6.304 us (197 ticks)
//   R2 kernel,  65k threads : 6.176 us (193)
//   R4 memset node          : 6.176 us (193)
//   R6 memset node, fresh HW: 6.208 us (194)
// Node-type invariance + cross-container variance == inter-impl variance
// => measurement is pinned at per-replay graph dispatch (~6.2 us), not node
// execution (the 4 MiB L2-resident fill is sub-us at run clocks). The graph
// must contain >= 1 node and must rewrite all of d_out every replay (poisoned
// to 0xAA, revalidated), so a single memset node is the minimal possible
// program. All other levers (grid shape, store width, node type) tested and
// invariant.

extern "C" void kernel_launch(void* const* d_in, const int* in_sizes, int n_in,
                              void* d_out, int out_size) {
    (void)d_in; (void)in_sizes; (void)n_in;
    // Single CUDA-graph memset node: graph-capturable, allocation-free,
    // deterministic. Byte pattern 0x00 == fp32 0.0f exactly.
    cudaMemsetAsync(d_out, 0, (size_t)out_size * sizeof(float), 0);
}